// round 1
// baseline (speedup 1.0000x reference)
#include <cuda_runtime.h>
#include <math.h>

#define MIN_ROUGHNESS 0.08f
#define MAX_ROUGHNESS 0.5f
#define N_MIPS 6

struct SpecTable {
    const float* p[N_MIPS];
};

struct float3x { float x, y, z; };

__device__ __forceinline__ float3x cube_sample_bilinear(const float* __restrict__ tex,
                                                        int R, int face, float u, float v) {
    float Rf = (float)R;
    float tu = (u * 0.5f + 0.5f) * Rf - 0.5f;
    float tv = (v * 0.5f + 0.5f) * Rf - 0.5f;
    float x0f = floorf(tu);
    float y0f = floorf(tv);
    float fx = tu - x0f;
    float fy = tv - y0f;
    int x0 = (int)fminf(fmaxf(x0f, 0.0f), Rf - 1.0f);
    int x1 = (int)fminf(fmaxf(x0f + 1.0f, 0.0f), Rf - 1.0f);
    int y0 = (int)fminf(fmaxf(y0f, 0.0f), Rf - 1.0f);
    int y1 = (int)fminf(fmaxf(y0f + 1.0f, 0.0f), Rf - 1.0f);

    int baseF = face * R * R;
    int i00 = (baseF + y0 * R + x0) * 3;
    int i01 = (baseF + y0 * R + x1) * 3;
    int i10 = (baseF + y1 * R + x0) * 3;
    int i11 = (baseF + y1 * R + x1) * 3;

    float w00 = (1.0f - fx) * (1.0f - fy);
    float w01 = fx * (1.0f - fy);
    float w10 = (1.0f - fx) * fy;
    float w11 = fx * fy;

    float3x r;
    r.x = __ldg(tex + i00 + 0) * w00 + __ldg(tex + i01 + 0) * w01 +
          __ldg(tex + i10 + 0) * w10 + __ldg(tex + i11 + 0) * w11;
    r.y = __ldg(tex + i00 + 1) * w00 + __ldg(tex + i01 + 1) * w01 +
          __ldg(tex + i10 + 1) * w10 + __ldg(tex + i11 + 1) * w11;
    r.z = __ldg(tex + i00 + 2) * w00 + __ldg(tex + i01 + 2) * w01 +
          __ldg(tex + i10 + 2) * w10 + __ldg(tex + i11 + 2) * w11;
    return r;
}

__device__ __forceinline__ void cube_face_uv(float x, float y, float z,
                                             int& face, float& u, float& v) {
    float ax = fabsf(x), ay = fabsf(y), az = fabsf(z);
    bool is_x = (ax >= ay) && (ax >= az);
    bool is_y = (!is_x) && (ay >= az);
    face = is_x ? (x >= 0.0f ? 0 : 1)
                : (is_y ? (y >= 0.0f ? 2 : 3)
                        : (z >= 0.0f ? 4 : 5));
    float ma = fmaxf(is_x ? ax : (is_y ? ay : az), 1e-20f);
    float un = (face == 0) ? -z : (face == 1) ? z : (face == 5) ? -x : x;
    float vn = (face == 2) ? z : (face == 3) ? -z : -y;
    float inv = 1.0f / ma;
    u = un * inv;
    v = vn * inv;
}

__device__ __forceinline__ float linear2srgb(float x) {
    // reference: where(x > 0.0031308, 1.055*x^(1/2.4)-0.055, 12.92*x)
    if (x > 0.0031308f) {
        return 1.055f * powf(x, 1.0f / 2.4f) - 0.055f;
    }
    return 12.92f * x;
}

__global__ void __launch_bounds__(256)
envlight_kernel(const float* __restrict__ gb_pos,
                const float* __restrict__ gb_normal,
                const float* __restrict__ basecolor,
                const float* __restrict__ metallic,
                const float* __restrict__ roughness,
                const float* __restrict__ view_pos,
                const float* __restrict__ diffuse_cube,   // 6x16x16x3
                const float* __restrict__ fg_lut,          // 256x256x2
                SpecTable specs,
                float* __restrict__ out,
                int n) {
    int i = blockIdx.x * blockDim.x + threadIdx.x;
    if (i >= n) return;

    // ---- load G-buffer ----
    float px = gb_pos[i * 3 + 0];
    float py = gb_pos[i * 3 + 1];
    float pz = gb_pos[i * 3 + 2];
    float nx = gb_normal[i * 3 + 0];
    float ny = gb_normal[i * 3 + 1];
    float nz = gb_normal[i * 3 + 2];
    float bcx = basecolor[i * 3 + 0];
    float bcy = basecolor[i * 3 + 1];
    float bcz = basecolor[i * 3 + 2];
    float met = metallic[i];
    float rough = roughness[i];

    float vx = __ldg(view_pos + 0);
    float vy = __ldg(view_pos + 1);
    float vz = __ldg(view_pos + 2);

    // ---- wo = normalize(view - pos) ----
    float wx = vx - px, wy = vy - py, wz = vz - pz;
    float wlen2 = fmaxf(wx * wx + wy * wy + wz * wz, 1e-20f);
    float winv = rsqrtf(wlen2);
    wx *= winv; wy *= winv; wz *= winv;

    // ---- albedos ----
    float om = 1.0f - met;
    float dax = om * bcx, day = om * bcy, daz = om * bcz;
    float sax = 0.04f * om + met * bcx;
    float say = 0.04f * om + met * bcy;
    float saz = 0.04f * om + met * bcz;

    // ---- reflection vector ----
    float d = wx * nx + wy * ny + wz * nz;      // dot(wo, normal)
    float rx = 2.0f * d * nx - wx;
    float ry = 2.0f * d * ny - wy;
    float rz = 2.0f * d * nz - wz;
    float rlen2 = fmaxf(rx * rx + ry * ry + rz * rz, 1e-20f);
    float rinv = rsqrtf(rlen2);
    rx *= rinv; ry *= rinv; rz *= rinv;

    // ---- ambient = sample diffuse cubemap at normal ----
    int dface; float du, dv;
    cube_face_uv(nx, ny, nz, dface, du, dv);
    float3x ambient = cube_sample_bilinear(diffuse_cube, 16, dface, du, dv);

    float dlx = ambient.x * dax;
    float dly = ambient.y * day;
    float dlz = ambient.z * daz;

    // ---- FG LUT sample: uv = (NdotV, roughness), 256x256x2, clamp ----
    float NdotV = fmaxf(d, 0.0001f);
    {
        // _sample_2d_clamp
    }
    float fg0, fg1;
    {
        const int W = 256, H = 256;
        float tu = NdotV * (float)W - 0.5f;
        float tv = rough * (float)H - 0.5f;
        float x0f = floorf(tu);
        float y0f = floorf(tv);
        float fx = tu - x0f;
        float fy = tv - y0f;
        int x0 = (int)fminf(fmaxf(x0f, 0.0f), (float)(W - 1));
        int x1 = (int)fminf(fmaxf(x0f + 1.0f, 0.0f), (float)(W - 1));
        int y0 = (int)fminf(fmaxf(y0f, 0.0f), (float)(H - 1));
        int y1 = (int)fminf(fmaxf(y0f + 1.0f, 0.0f), (float)(H - 1));
        int i00 = (y0 * W + x0) * 2;
        int i01 = (y0 * W + x1) * 2;
        int i10 = (y1 * W + x0) * 2;
        int i11 = (y1 * W + x1) * 2;
        float w00 = (1.0f - fx) * (1.0f - fy);
        float w01 = fx * (1.0f - fy);
        float w10 = (1.0f - fx) * fy;
        float w11 = fx * fy;
        fg0 = __ldg(fg_lut + i00 + 0) * w00 + __ldg(fg_lut + i01 + 0) * w01 +
              __ldg(fg_lut + i10 + 0) * w10 + __ldg(fg_lut + i11 + 0) * w11;
        fg1 = __ldg(fg_lut + i00 + 1) * w00 + __ldg(fg_lut + i01 + 1) * w01 +
              __ldg(fg_lut + i10 + 1) * w10 + __ldg(fg_lut + i11 + 1) * w11;
    }

    // ---- mip level from roughness ----
    float mip;
    {
        const float L = (float)N_MIPS;
        float lo = (fminf(fmaxf(rough, MIN_ROUGHNESS), MAX_ROUGHNESS) - MIN_ROUGHNESS)
                   / (MAX_ROUGHNESS - MIN_ROUGHNESS) * (L - 2.0f);
        float hi = (fminf(fmaxf(rough, MAX_ROUGHNESS), 1.0f) - MAX_ROUGHNESS)
                   / (1.0f - MAX_ROUGHNESS) + (L - 2.0f);
        mip = (rough < MAX_ROUGHNESS) ? lo : hi;
        mip = fminf(fmaxf(mip, 0.0f), L - 1.0f);
    }

    // ---- specular: only two adjacent levels have nonzero triangle weight ----
    int sface; float su, sv;
    cube_face_uv(rx, ry, rz, sface, su, sv);

    int l0 = (int)floorf(mip);
    if (l0 > N_MIPS - 1) l0 = N_MIPS - 1;
    float f = mip - (float)l0;
    int l1 = l0 + 1;
    if (l1 > N_MIPS - 1) l1 = N_MIPS - 1;   // f==0 in that case

    const float* t0 = specs.p[l0];
    const float* t1 = specs.p[l1];
    int R0 = 512 >> l0;
    int R1 = 512 >> l1;

    float3x s0 = cube_sample_bilinear(t0, R0, sface, su, sv);
    float3x s1 = cube_sample_bilinear(t1, R1, sface, su, sv);

    float spx = (1.0f - f) * s0.x + f * s1.x;
    float spy = (1.0f - f) * s0.y + f * s1.y;
    float spz = (1.0f - f) * s0.z + f * s1.z;

    // ---- combine ----
    float refx = sax * fg0 + fg1;
    float refy = say * fg0 + fg1;
    float refz = saz * fg0 + fg1;

    float ox = fminf(fmaxf(spx * refx + dlx, 0.0f), 1.0f);
    float oy = fminf(fmaxf(spy * refy + dly, 0.0f), 1.0f);
    float oz = fminf(fmaxf(spz * refz + dlz, 0.0f), 1.0f);

    out[i * 3 + 0] = linear2srgb(ox);
    out[i * 3 + 1] = linear2srgb(oy);
    out[i * 3 + 2] = linear2srgb(oz);
}

extern "C" void kernel_launch(void* const* d_in, const int* in_sizes, int n_in,
                              void* d_out, int out_size) {
    const float* gb_pos    = (const float*)d_in[0];
    const float* gb_normal = (const float*)d_in[1];
    const float* basecolor = (const float*)d_in[2];
    const float* metallic  = (const float*)d_in[3];
    const float* roughness = (const float*)d_in[4];
    const float* view_pos  = (const float*)d_in[5];
    const float* diffuse   = (const float*)d_in[6];
    const float* fg_lut    = (const float*)d_in[7];

    SpecTable specs;
    specs.p[0] = (const float*)d_in[8];
    specs.p[1] = (const float*)d_in[9];
    specs.p[2] = (const float*)d_in[10];
    specs.p[3] = (const float*)d_in[11];
    specs.p[4] = (const float*)d_in[12];
    specs.p[5] = (const float*)d_in[13];

    float* out = (float*)d_out;
    int n = in_sizes[0] / 3;   // number of pixels (gb_pos has 3 floats each)

    int threads = 256;
    int blocks = (n + threads - 1) / threads;
    envlight_kernel<<<blocks, threads>>>(gb_pos, gb_normal, basecolor, metallic,
                                         roughness, view_pos, diffuse, fg_lut,
                                         specs, out, n);
}

// round 2
// speedup vs baseline: 1.1148x; 1.1148x over previous
#include <cuda_runtime.h>
#include <math.h>

#define MIN_ROUGHNESS 0.08f
#define MAX_ROUGHNESS 0.5f
#define N_MIPS 6

struct SpecTable {
    const float* p[N_MIPS];
};

struct float3x { float x, y, z; };

__device__ __forceinline__ float3x cube_sample_bilinear(const float* __restrict__ tex,
                                                        int R, int face, float u, float v) {
    float Rf = (float)R;
    float tu = fmaf(u, 0.5f * Rf, 0.5f * Rf - 0.5f);
    float tv = fmaf(v, 0.5f * Rf, 0.5f * Rf - 0.5f);
    float x0f = floorf(tu);
    float y0f = floorf(tv);
    float fx = tu - x0f;
    float fy = tv - y0f;
    int x0 = (int)fminf(fmaxf(x0f, 0.0f), Rf - 1.0f);
    int x1 = (int)fminf(fmaxf(x0f + 1.0f, 0.0f), Rf - 1.0f);
    int y0 = (int)fminf(fmaxf(y0f, 0.0f), Rf - 1.0f);
    int y1 = (int)fminf(fmaxf(y0f + 1.0f, 0.0f), Rf - 1.0f);

    int baseF = face * R * R;
    int i00 = (baseF + y0 * R + x0) * 3;
    int i01 = (baseF + y0 * R + x1) * 3;
    int i10 = (baseF + y1 * R + x0) * 3;
    int i11 = (baseF + y1 * R + x1) * 3;

    float w00 = (1.0f - fx) * (1.0f - fy);
    float w01 = fx * (1.0f - fy);
    float w10 = (1.0f - fx) * fy;
    float w11 = fx * fy;

    float3x r;
    r.x = __ldg(tex + i00 + 0) * w00 + __ldg(tex + i01 + 0) * w01 +
          __ldg(tex + i10 + 0) * w10 + __ldg(tex + i11 + 0) * w11;
    r.y = __ldg(tex + i00 + 1) * w00 + __ldg(tex + i01 + 1) * w01 +
          __ldg(tex + i10 + 1) * w10 + __ldg(tex + i11 + 1) * w11;
    r.z = __ldg(tex + i00 + 2) * w00 + __ldg(tex + i01 + 2) * w01 +
          __ldg(tex + i10 + 2) * w10 + __ldg(tex + i11 + 2) * w11;
    return r;
}

__device__ __forceinline__ void cube_face_uv(float x, float y, float z,
                                             int& face, float& u, float& v) {
    float ax = fabsf(x), ay = fabsf(y), az = fabsf(z);
    bool is_x = (ax >= ay) && (ax >= az);
    bool is_y = (!is_x) && (ay >= az);
    face = is_x ? (x >= 0.0f ? 0 : 1)
                : (is_y ? (y >= 0.0f ? 2 : 3)
                        : (z >= 0.0f ? 4 : 5));
    float ma = fmaxf(is_x ? ax : (is_y ? ay : az), 1e-20f);
    float un = (face == 0) ? -z : (face == 1) ? z : (face == 5) ? -x : x;
    float vn = (face == 2) ? z : (face == 3) ? -z : -y;
    float inv = 1.0f / ma;
    u = un * inv;
    v = vn * inv;
}

__device__ __forceinline__ float linear2srgb(float x) {
    if (x > 0.0031308f) {
        return 1.055f * __powf(x, 1.0f / 2.4f) - 0.055f;
    }
    return 12.92f * x;
}

__device__ __forceinline__ void shade_pixel(
    float px, float py, float pz,
    float nx, float ny, float nz,
    float bcx, float bcy, float bcz,
    float met, float rough,
    float vx, float vy, float vz,
    const float* __restrict__ diffuse_cube,
    const float* __restrict__ fg_lut,
    const SpecTable& specs,
    float& ox, float& oy, float& oz)
{
    // wo = normalize(view - pos)
    float wx = vx - px, wy = vy - py, wz = vz - pz;
    float wlen2 = fmaxf(wx * wx + wy * wy + wz * wz, 1e-20f);
    float winv = rsqrtf(wlen2);
    wx *= winv; wy *= winv; wz *= winv;

    float om = 1.0f - met;
    float dax = om * bcx, day = om * bcy, daz = om * bcz;
    float sax = 0.04f * om + met * bcx;
    float say = 0.04f * om + met * bcy;
    float saz = 0.04f * om + met * bcz;

    float d = wx * nx + wy * ny + wz * nz;
    float rx = 2.0f * d * nx - wx;
    float ry = 2.0f * d * ny - wy;
    float rz = 2.0f * d * nz - wz;
    float rlen2 = fmaxf(rx * rx + ry * ry + rz * rz, 1e-20f);
    float rinv = rsqrtf(rlen2);
    rx *= rinv; ry *= rinv; rz *= rinv;

    // ambient from diffuse cubemap (16^2)
    int dface; float du, dv;
    cube_face_uv(nx, ny, nz, dface, du, dv);
    float3x ambient = cube_sample_bilinear(diffuse_cube, 16, dface, du, dv);

    float dlx = ambient.x * dax;
    float dly = ambient.y * day;
    float dlz = ambient.z * daz;

    // FG LUT (256x256x2, clamp)
    float NdotV = fmaxf(d, 0.0001f);
    float fg0, fg1;
    {
        const float Wf = 256.0f, Hf = 256.0f;
        float tu = NdotV * Wf - 0.5f;
        float tv = rough * Hf - 0.5f;
        float x0f = floorf(tu);
        float y0f = floorf(tv);
        float fx = tu - x0f;
        float fy = tv - y0f;
        int x0 = (int)fminf(fmaxf(x0f, 0.0f), 255.0f);
        int x1 = (int)fminf(fmaxf(x0f + 1.0f, 0.0f), 255.0f);
        int y0 = (int)fminf(fmaxf(y0f, 0.0f), 255.0f);
        int y1 = (int)fminf(fmaxf(y0f + 1.0f, 0.0f), 255.0f);
        int i00 = (y0 * 256 + x0) * 2;
        int i01 = (y0 * 256 + x1) * 2;
        int i10 = (y1 * 256 + x0) * 2;
        int i11 = (y1 * 256 + x1) * 2;
        float w00 = (1.0f - fx) * (1.0f - fy);
        float w01 = fx * (1.0f - fy);
        float w10 = (1.0f - fx) * fy;
        float w11 = fx * fy;
        // fg pairs are 8B-aligned: load as float2
        float2 c00 = __ldg((const float2*)(fg_lut + i00));
        float2 c01 = __ldg((const float2*)(fg_lut + i01));
        float2 c10 = __ldg((const float2*)(fg_lut + i10));
        float2 c11 = __ldg((const float2*)(fg_lut + i11));
        fg0 = c00.x * w00 + c01.x * w01 + c10.x * w10 + c11.x * w11;
        fg1 = c00.y * w00 + c01.y * w01 + c10.y * w10 + c11.y * w11;
    }

    // mip
    float mip;
    {
        const float L = (float)N_MIPS;
        float lo = (fminf(fmaxf(rough, MIN_ROUGHNESS), MAX_ROUGHNESS) - MIN_ROUGHNESS)
                   * ((L - 2.0f) / (MAX_ROUGHNESS - MIN_ROUGHNESS));
        float hi = (fminf(fmaxf(rough, MAX_ROUGHNESS), 1.0f) - MAX_ROUGHNESS)
                   * (1.0f / (1.0f - MAX_ROUGHNESS)) + (L - 2.0f);
        mip = (rough < MAX_ROUGHNESS) ? lo : hi;
        mip = fminf(fmaxf(mip, 0.0f), L - 1.0f);
    }

    int sface; float su, sv;
    cube_face_uv(rx, ry, rz, sface, su, sv);

    int l0 = (int)floorf(mip);
    if (l0 > N_MIPS - 1) l0 = N_MIPS - 1;
    float f = mip - (float)l0;
    int l1 = l0 + 1;
    if (l1 > N_MIPS - 1) l1 = N_MIPS - 1;

    const float* t0 = specs.p[l0];
    const float* t1 = specs.p[l1];
    int R0 = 512 >> l0;
    int R1 = 512 >> l1;

    float3x s0 = cube_sample_bilinear(t0, R0, sface, su, sv);
    float3x s1 = cube_sample_bilinear(t1, R1, sface, su, sv);

    float spx = (1.0f - f) * s0.x + f * s1.x;
    float spy = (1.0f - f) * s0.y + f * s1.y;
    float spz = (1.0f - f) * s0.z + f * s1.z;

    float refx = sax * fg0 + fg1;
    float refy = say * fg0 + fg1;
    float refz = saz * fg0 + fg1;

    float cx = fminf(fmaxf(spx * refx + dlx, 0.0f), 1.0f);
    float cy = fminf(fmaxf(spy * refy + dly, 0.0f), 1.0f);
    float cz = fminf(fmaxf(spz * refz + dlz, 0.0f), 1.0f);

    ox = linear2srgb(cx);
    oy = linear2srgb(cy);
    oz = linear2srgb(cz);
}

__global__ void __launch_bounds__(256)
envlight_kernel4(const float* __restrict__ gb_pos,
                 const float* __restrict__ gb_normal,
                 const float* __restrict__ basecolor,
                 const float* __restrict__ metallic,
                 const float* __restrict__ roughness,
                 const float* __restrict__ view_pos,
                 const float* __restrict__ diffuse_cube,
                 const float* __restrict__ fg_lut,
                 SpecTable specs,
                 float* __restrict__ out,
                 int n) {
    int q = blockIdx.x * blockDim.x + threadIdx.x;
    int base = q * 4;
    if (base >= n) return;

    float vx = __ldg(view_pos + 0);
    float vy = __ldg(view_pos + 1);
    float vz = __ldg(view_pos + 2);

    float P[12], N[12], BC[12], MET[4], RGH[4];
    bool full = (base + 4 <= n);

    if (full) {
        const float4* p4 = (const float4*)gb_pos + q * 3;
        const float4* n4 = (const float4*)gb_normal + q * 3;
        const float4* b4 = (const float4*)basecolor + q * 3;
        #pragma unroll
        for (int k = 0; k < 3; k++) {
            float4 a = __ldg(p4 + k);
            P[k * 4 + 0] = a.x; P[k * 4 + 1] = a.y; P[k * 4 + 2] = a.z; P[k * 4 + 3] = a.w;
            float4 b = __ldg(n4 + k);
            N[k * 4 + 0] = b.x; N[k * 4 + 1] = b.y; N[k * 4 + 2] = b.z; N[k * 4 + 3] = b.w;
            float4 c = __ldg(b4 + k);
            BC[k * 4 + 0] = c.x; BC[k * 4 + 1] = c.y; BC[k * 4 + 2] = c.z; BC[k * 4 + 3] = c.w;
        }
        float4 m = __ldg((const float4*)metallic + q);
        MET[0] = m.x; MET[1] = m.y; MET[2] = m.z; MET[3] = m.w;
        float4 r = __ldg((const float4*)roughness + q);
        RGH[0] = r.x; RGH[1] = r.y; RGH[2] = r.z; RGH[3] = r.w;
    } else {
        #pragma unroll
        for (int k = 0; k < 4; k++) {
            int i = base + k;
            if (i < n) {
                P[k * 3 + 0] = gb_pos[i * 3 + 0]; // note: tail path uses [k*3..] layout below
            }
        }
        // tail: reload in interleaved layout matching the full path
        #pragma unroll
        for (int k = 0; k < 4; k++) {
            int i = base + k;
            int ii = (i < n) ? i : (n - 1);
            // layout: element j of pixel k lives at flattened index k + 4*?? — simpler:
            // store pixel-major into a second indexing scheme handled in loop below.
            P[k] = gb_pos[ii * 3 + 0]; P[4 + k] = gb_pos[ii * 3 + 1]; P[8 + k] = gb_pos[ii * 3 + 2];
            N[k] = gb_normal[ii * 3 + 0]; N[4 + k] = gb_normal[ii * 3 + 1]; N[8 + k] = gb_normal[ii * 3 + 2];
            BC[k] = basecolor[ii * 3 + 0]; BC[4 + k] = basecolor[ii * 3 + 1]; BC[8 + k] = basecolor[ii * 3 + 2];
            MET[k] = metallic[ii];
            RGH[k] = roughness[ii];
        }
    }

    float O[12];
    #pragma unroll
    for (int k = 0; k < 4; k++) {
        // flat index of pixel k's channel c within the 3-float4 block:
        // full path loaded flattened floats [0..11] = pixels' AoS stream:
        // pixel k channels at flat positions 3k, 3k+1, 3k+2
        float px, py, pz, nx, ny, nz, bx, by, bz;
        if (full) {
            px = P[3 * k + 0]; py = P[3 * k + 1]; pz = P[3 * k + 2];
            nx = N[3 * k + 0]; ny = N[3 * k + 1]; nz = N[3 * k + 2];
            bx = BC[3 * k + 0]; by = BC[3 * k + 1]; bz = BC[3 * k + 2];
        } else {
            px = P[k]; py = P[4 + k]; pz = P[8 + k];
            nx = N[k]; ny = N[4 + k]; nz = N[8 + k];
            bx = BC[k]; by = BC[4 + k]; bz = BC[8 + k];
        }
        float ox, oy, oz;
        shade_pixel(px, py, pz, nx, ny, nz, bx, by, bz,
                    MET[k], RGH[k], vx, vy, vz,
                    diffuse_cube, fg_lut, specs, ox, oy, oz);
        O[3 * k + 0] = ox; O[3 * k + 1] = oy; O[3 * k + 2] = oz;
    }

    if (full) {
        float4* o4 = (float4*)out + q * 3;
        #pragma unroll
        for (int k = 0; k < 3; k++) {
            float4 w;
            w.x = O[k * 4 + 0]; w.y = O[k * 4 + 1]; w.z = O[k * 4 + 2]; w.w = O[k * 4 + 3];
            o4[k] = w;
        }
    } else {
        #pragma unroll
        for (int k = 0; k < 4; k++) {
            int i = base + k;
            if (i < n) {
                out[i * 3 + 0] = O[3 * k + 0];
                out[i * 3 + 1] = O[3 * k + 1];
                out[i * 3 + 2] = O[3 * k + 2];
            }
        }
    }
}

extern "C" void kernel_launch(void* const* d_in, const int* in_sizes, int n_in,
                              void* d_out, int out_size) {
    const float* gb_pos    = (const float*)d_in[0];
    const float* gb_normal = (const float*)d_in[1];
    const float* basecolor = (const float*)d_in[2];
    const float* metallic  = (const float*)d_in[3];
    const float* roughness = (const float*)d_in[4];
    const float* view_pos  = (const float*)d_in[5];
    const float* diffuse   = (const float*)d_in[6];
    const float* fg_lut    = (const float*)d_in[7];

    SpecTable specs;
    specs.p[0] = (const float*)d_in[8];
    specs.p[1] = (const float*)d_in[9];
    specs.p[2] = (const float*)d_in[10];
    specs.p[3] = (const float*)d_in[11];
    specs.p[4] = (const float*)d_in[12];
    specs.p[5] = (const float*)d_in[13];

    float* out = (float*)d_out;
    int n = in_sizes[0] / 3;

    int threads = 256;
    int quads = (n + 3) / 4;
    int blocks = (quads + threads - 1) / threads;
    envlight_kernel4<<<blocks, threads>>>(gb_pos, gb_normal, basecolor, metallic,
                                          roughness, view_pos, diffuse, fg_lut,
                                          specs, out, n);
}